// round 15
// baseline (speedup 1.0000x reference)
#include <cuda_runtime.h>
#include <cuda_bf16.h>
#include <mma.h>
#include <cstdint>

using namespace nvcuda;

#define N_NODES 25000
#define E_EDGES 200000
#define HID 512
#define MT 196
#define MPAD (MT * 128)        // 25088
#define SCAN_B 25

// ---------------------------------------------------------------------------
// Scratch (allocation-free: __device__ globals)
// ---------------------------------------------------------------------------
__device__ float g_bufA[MPAD * HID];
__device__ float g_dis[N_NODES];
__device__ int   g_cnt[N_NODES];
__device__ int   g_off[N_NODES + 1];
__device__ int   g_cur[N_NODES];
__device__ int   g_part[SCAN_B];
__device__ int   g_boff[SCAN_B];
__device__ int   g_csr_src[E_EDGES];
__device__ float g_csr_nrm[E_EDGES];
__device__ __nv_bfloat16 g_Ah[MPAD * HID];
__device__ __nv_bfloat16 g_Al[MPAD * HID];
__device__ __nv_bfloat16 g_B1h[HID * HID];
__device__ __nv_bfloat16 g_B1l[HID * HID];
__device__ __nv_bfloat16 g_B2h[HID * HID];
__device__ __nv_bfloat16 g_B2l[HID * HID];

// ---------------------------------------------------------------------------
// CSR build (distributed scan)
// ---------------------------------------------------------------------------
__global__ void cnt_count_kernel(const int* __restrict__ dst, int* cnt) {
    int e = blockIdx.x * blockDim.x + threadIdx.x;
    if (e < E_EDGES) atomicAdd(&cnt[dst[e]], 1);
}

__global__ __launch_bounds__(1024)
void scan_part_kernel(const int* __restrict__ cnt, int* __restrict__ off,
                      int* __restrict__ part, float* __restrict__ dis) {
    __shared__ int wsum[32];
    int b = blockIdx.x, t = threadIdx.x, lane = t & 31, warp = t >> 5;
    int idx = b * 1024 + t;
    int v = (idx < N_NODES) ? cnt[idx] : 0;
    if (idx < N_NODES) dis[idx] = rsqrtf((float)v + 1.0f);

    int incl = v;
    #pragma unroll
    for (int d = 1; d < 32; d <<= 1) {
        int u = __shfl_up_sync(0xffffffff, incl, d);
        if (lane >= d) incl += u;
    }
    if (lane == 31) wsum[warp] = incl;
    __syncthreads();
    if (warp == 0) {
        int w = wsum[lane];
        #pragma unroll
        for (int d = 1; d < 32; d <<= 1) {
            int u = __shfl_up_sync(0xffffffff, w, d);
            if (lane >= d) w += u;
        }
        wsum[lane] = w;
    }
    __syncthreads();
    int excl = incl - v + (warp ? wsum[warp - 1] : 0);
    if (idx < N_NODES) off[idx] = excl;
    if (t == 1023) part[b] = wsum[31];
}

__global__ void scan_top_kernel(const int* __restrict__ part, int* __restrict__ boff,
                                int* __restrict__ off) {
    int lane = threadIdx.x;
    int v = (lane < SCAN_B) ? part[lane] : 0;
    int incl = v;
    #pragma unroll
    for (int d = 1; d < 32; d <<= 1) {
        int u = __shfl_up_sync(0xffffffff, incl, d);
        if (lane >= d) incl += u;
    }
    if (lane < SCAN_B) boff[lane] = incl - v;
    if (lane == 31) off[N_NODES] = incl;
}

__global__ __launch_bounds__(1024)
void scan_apply_kernel(int* __restrict__ off, const int* __restrict__ boff,
                       int* __restrict__ cur) {
    int b = blockIdx.x, t = threadIdx.x;
    int idx = b * 1024 + t;
    if (idx < N_NODES) {
        int o = off[idx] + boff[b];
        off[idx] = o;
        cur[idx] = o;
    }
}

// scatter also precomputes per-edge symmetric norm (dis is ready by now)
__global__ void scatter_kernel(const int* __restrict__ src, const int* __restrict__ dst,
                               int* cur, int* __restrict__ csr_src,
                               float* __restrict__ csr_nrm,
                               const float* __restrict__ dis) {
    int e = blockIdx.x * blockDim.x + threadIdx.x;
    if (e >= E_EDGES) return;
    int s = src[e], d = dst[e];
    int pos = atomicAdd(&cur[d], 1);
    csr_src[pos] = s;
    csr_nrm[pos] = __ldg(&dis[s]) * __ldg(&dis[d]);
}

// ---------------------------------------------------------------------------
// Packing (float4/thread)
// ---------------------------------------------------------------------------
__device__ __forceinline__ void split4_store(float r0, float r1, float r2, float r3,
                                             __nv_bfloat16* outH, __nv_bfloat16* outL,
                                             size_t o) {
    __nv_bfloat16 h0 = __float2bfloat16_rn(r0), h1 = __float2bfloat16_rn(r1);
    __nv_bfloat16 h2 = __float2bfloat16_rn(r2), h3 = __float2bfloat16_rn(r3);
    __nv_bfloat16 l0 = __float2bfloat16_rn(r0 - __bfloat162float(h0));
    __nv_bfloat16 l1 = __float2bfloat16_rn(r1 - __bfloat162float(h1));
    __nv_bfloat16 l2 = __float2bfloat16_rn(r2 - __bfloat162float(h2));
    __nv_bfloat16 l3 = __float2bfloat16_rn(r3 - __bfloat162float(h3));
    __nv_bfloat162 ph0(h0, h1), ph1(h2, h3), pl0(l0, l1), pl1(l2, l3);
    uint2 uh = make_uint2(*(uint32_t*)&ph0, *(uint32_t*)&ph1);
    uint2 ul = make_uint2(*(uint32_t*)&pl0, *(uint32_t*)&pl1);
    *(uint2*)(outH + o) = uh;
    *(uint2*)(outL + o) = ul;
}

__global__ __launch_bounds__(256)
void pack_x_kernel(const float* __restrict__ src,
                   __nv_bfloat16* __restrict__ outH, __nv_bfloat16* __restrict__ outL) {
    int idx = blockIdx.x * blockDim.x + threadIdx.x;
    if (idx >= MPAD * 128) return;
    int m = idx >> 7;
    int k = (idx & 127) * 4;

    float4 v = make_float4(0.f, 0.f, 0.f, 0.f);
    if (m < N_NODES) v = *(const float4*)(src + (size_t)m * HID + k);
    split4_store(v.x, v.y, v.z, v.w, outH, outL, (size_t)m * HID + k);
}

__global__ __launch_bounds__(256)
void pack_w2x_kernel(const float* __restrict__ W1,
                     __nv_bfloat16* __restrict__ o1H, __nv_bfloat16* __restrict__ o1L,
                     const float* __restrict__ W2,
                     __nv_bfloat16* __restrict__ o2H, __nv_bfloat16* __restrict__ o2L) {
    int idx = blockIdx.x * blockDim.x + threadIdx.x;
    if (idx >= 2 * 512 * 128) return;
    int z = idx >= 512 * 128;
    int r = z ? idx - 512 * 128 : idx;
    int k = r >> 7;
    int n = (r & 127) * 4;

    const float* W = z ? W2 : W1;
    __nv_bfloat16* oH = z ? o2H : o1H;
    __nv_bfloat16* oL = z ? o2L : o1L;

    float4 v = *(const float4*)(W + (size_t)k * HID + n);
    split4_store(v.x, v.y, v.z, v.w, oH, oL, (size_t)k * HID + n);
}

// ---------------------------------------------------------------------------
// cp.async helpers
// ---------------------------------------------------------------------------
__device__ __forceinline__ void cpa16(uint32_t dst, const void* src) {
    asm volatile("cp.async.cg.shared.global [%0], [%1], 16;" :: "r"(dst), "l"(src));
}
__device__ __forceinline__ void cpa_commit() {
    asm volatile("cp.async.commit_group;" ::: "memory");
}
__device__ __forceinline__ void cpa_wait0() {
    asm volatile("cp.async.wait_group 0;" ::: "memory");
}

// ---------------------------------------------------------------------------
// WMMA bf16-split GEMM (known-good). DO NOT grow smem (2-CTA/SM, R8/R10);
// DO NOT split M (wave quantization, R13).
// ---------------------------------------------------------------------------
#define AS_STRIDE 40
#define BS_STRIDE 136
#define A_TILE_ELE (128 * AS_STRIDE)
#define B_TILE_ELE (32 * BS_STRIDE)
#define STAGE_ELE  (2 * A_TILE_ELE + 2 * B_TILE_ELE)
#define GEMM_SMEM_BYTES (2 * STAGE_ELE * 2)

__global__ __launch_bounds__(256, 2)
void gemm_wmma_kernel(const __nv_bfloat16* __restrict__ Ah, const __nv_bfloat16* __restrict__ Al,
                      const __nv_bfloat16* __restrict__ Bh, const __nv_bfloat16* __restrict__ Bl,
                      float* __restrict__ C) {
    extern __shared__ __nv_bfloat16 smem[];

    int tid = threadIdx.x;
    int bm = blockIdx.y * 128;
    int bn = blockIdx.x * 128;
    int wid = tid >> 5;
    int wm = (wid & 3) * 32;
    int wn = (wid >> 2) * 64;

    wmma::fragment<wmma::accumulator, 16, 16, 16, float> acc[2][4];
    #pragma unroll
    for (int i = 0; i < 2; i++)
        #pragma unroll
        for (int j = 0; j < 4; j++)
            wmma::fill_fragment(acc[i][j], 0.0f);

    int a_r0 = tid >> 2,  a_c0 = (tid & 3) * 8;
    int a_r1 = (tid + 256) >> 2, a_c1 = ((tid + 256) & 3) * 8;
    int b_r0 = tid >> 4,  b_c0 = (tid & 15) * 8;
    int b_r1 = (tid + 256) >> 4, b_c1 = ((tid + 256) & 15) * 8;

    uint32_t sbase = (uint32_t)__cvta_generic_to_shared(smem);

    auto load_stage = [&](int stage, int k0) {
        uint32_t st = sbase + (uint32_t)(stage * STAGE_ELE) * 2;
        uint32_t sAh = st;
        uint32_t sAl = st + A_TILE_ELE * 2;
        uint32_t sBh = st + 2 * A_TILE_ELE * 2;
        uint32_t sBl = st + (2 * A_TILE_ELE + B_TILE_ELE) * 2;

        const __nv_bfloat16* gA = Ah + (size_t)bm * HID + k0;
        const __nv_bfloat16* gAl2 = Al + (size_t)bm * HID + k0;
        const __nv_bfloat16* gB = Bh + (size_t)k0 * HID + bn;
        const __nv_bfloat16* gBl2 = Bl + (size_t)k0 * HID + bn;

        cpa16(sAh + (uint32_t)(a_r0 * AS_STRIDE + a_c0) * 2, gA  + (size_t)a_r0 * HID + a_c0);
        cpa16(sAh + (uint32_t)(a_r1 * AS_STRIDE + a_c1) * 2, gA  + (size_t)a_r1 * HID + a_c1);
        cpa16(sAl + (uint32_t)(a_r0 * AS_STRIDE + a_c0) * 2, gAl2 + (size_t)a_r0 * HID + a_c0);
        cpa16(sAl + (uint32_t)(a_r1 * AS_STRIDE + a_c1) * 2, gAl2 + (size_t)a_r1 * HID + a_c1);
        cpa16(sBh + (uint32_t)(b_r0 * BS_STRIDE + b_c0) * 2, gB  + (size_t)b_r0 * HID + b_c0);
        cpa16(sBh + (uint32_t)(b_r1 * BS_STRIDE + b_c1) * 2, gB  + (size_t)b_r1 * HID + b_c1);
        cpa16(sBl + (uint32_t)(b_r0 * BS_STRIDE + b_c0) * 2, gBl2 + (size_t)b_r0 * HID + b_c0);
        cpa16(sBl + (uint32_t)(b_r1 * BS_STRIDE + b_c1) * 2, gBl2 + (size_t)b_r1 * HID + b_c1);
        cpa_commit();
    };

    load_stage(0, 0);
    int buf = 0;

    for (int it = 0; it < 16; it++) {
        cpa_wait0();
        __syncthreads();
        if (it + 1 < 16) load_stage(buf ^ 1, (it + 1) * 32);

        __nv_bfloat16* st = smem + buf * STAGE_ELE;
        __nv_bfloat16* Ash = st;
        __nv_bfloat16* Asl = st + A_TILE_ELE;
        __nv_bfloat16* Bsh = st + 2 * A_TILE_ELE;
        __nv_bfloat16* Bsl = st + 2 * A_TILE_ELE + B_TILE_ELE;

        #pragma unroll
        for (int kk = 0; kk < 32; kk += 16) {
            wmma::fragment<wmma::matrix_a, 16, 16, 16, __nv_bfloat16, wmma::row_major> fa_h[2], fa_l[2];
            wmma::fragment<wmma::matrix_b, 16, 16, 16, __nv_bfloat16, wmma::row_major> fb_h[4], fb_l[4];
            #pragma unroll
            for (int i = 0; i < 2; i++) {
                wmma::load_matrix_sync(fa_h[i], Ash + (wm + i * 16) * AS_STRIDE + kk, AS_STRIDE);
                wmma::load_matrix_sync(fa_l[i], Asl + (wm + i * 16) * AS_STRIDE + kk, AS_STRIDE);
            }
            #pragma unroll
            for (int j = 0; j < 4; j++) {
                wmma::load_matrix_sync(fb_h[j], Bsh + kk * BS_STRIDE + wn + j * 16, BS_STRIDE);
                wmma::load_matrix_sync(fb_l[j], Bsl + kk * BS_STRIDE + wn + j * 16, BS_STRIDE);
            }
            #pragma unroll
            for (int i = 0; i < 2; i++)
                #pragma unroll
                for (int j = 0; j < 4; j++) {
                    wmma::mma_sync(acc[i][j], fa_h[i], fb_h[j], acc[i][j]);
                    wmma::mma_sync(acc[i][j], fa_l[i], fb_h[j], acc[i][j]);
                    wmma::mma_sync(acc[i][j], fa_h[i], fb_l[j], acc[i][j]);
                }
        }
        buf ^= 1;
    }

    #pragma unroll
    for (int i = 0; i < 2; i++)
        #pragma unroll
        for (int j = 0; j < 4; j++)
            wmma::store_matrix_sync(C + (size_t)(bm + wm + i * 16) * HID + bn + wn + j * 16,
                                    acc[i][j], HID, wmma::mem_row_major);
}

// ---------------------------------------------------------------------------
// Gather: 2 nodes per 256-thread block; precomputed per-edge norms;
// warp-shuffle broadcast (no barriers in the inner loop).
// ---------------------------------------------------------------------------
__device__ __forceinline__ float4 gather_node(const float* __restrict__ hw,
                                              const int* __restrict__ off,
                                              const int* __restrict__ csr_src,
                                              const float* __restrict__ csr_nrm,
                                              const float* __restrict__ dis,
                                              int n, int lt) {
    float dn = __ldg(&dis[n]);
    const float4* hn = (const float4*)(hw + (size_t)n * HID);
    float4 v = hn[lt];
    float dd = dn * dn;
    float4 acc = make_float4(v.x * dd, v.y * dd, v.z * dd, v.w * dd);

    int lane = lt & 31;
    int beg = __ldg(&off[n]), end = __ldg(&off[n + 1]);
    for (int base = beg; base < end; base += 32) {
        int m = min(32, end - base);
        int s = 0; float nrm = 0.f;
        if (lane < m) {
            s   = __ldg(&csr_src[base + lane]);
            nrm = __ldg(&csr_nrm[base + lane]);
        }
        #pragma unroll 8
        for (int j = 0; j < m; j++) {
            int sj   = __shfl_sync(0xffffffff, s, j);
            float nj = __shfl_sync(0xffffffff, nrm, j);
            float4 h = ((const float4*)(hw + (size_t)sj * HID))[lt];
            acc.x = fmaf(h.x, nj, acc.x);
            acc.y = fmaf(h.y, nj, acc.y);
            acc.z = fmaf(h.z, nj, acc.z);
            acc.w = fmaf(h.w, nj, acc.w);
        }
    }
    return acc;
}

__global__ __launch_bounds__(256)
void gather_pack_kernel(const float* __restrict__ hw,
                        const int* __restrict__ off, const int* __restrict__ csr_src,
                        const float* __restrict__ csr_nrm, const float* __restrict__ dis,
                        const float* __restrict__ bias,
                        __nv_bfloat16* __restrict__ outH, __nv_bfloat16* __restrict__ outL) {
    int t = threadIdx.x;
    int n = blockIdx.x * 2 + (t >> 7);
    int lt = t & 127;
    if (n >= N_NODES) return;

    float4 acc = gather_node(hw, off, csr_src, csr_nrm, dis, n, lt);

    int c = lt * 4;
    float4 b = *(const float4*)(bias + c);
    float r0 = fmaxf(acc.x + b.x, 0.f);
    float r1 = fmaxf(acc.y + b.y, 0.f);
    float r2 = fmaxf(acc.z + b.z, 0.f);
    float r3 = fmaxf(acc.w + b.w, 0.f);

    split4_store(r0, r1, r2, r3, outH, outL, (size_t)n * HID + c);
}

__global__ __launch_bounds__(256)
void gather_heads_kernel(const float* __restrict__ hw,
                         const int* __restrict__ off, const int* __restrict__ csr_src,
                         const float* __restrict__ csr_nrm, const float* __restrict__ dis,
                         const float* __restrict__ bias,
                         const float* __restrict__ Wo, const float* __restrict__ bo,
                         const float* __restrict__ Ww, const float* __restrict__ bw,
                         float* __restrict__ out) {
    __shared__ float red[16];
    int t = threadIdx.x;
    int n = blockIdx.x * 2 + (t >> 7);
    int lt = t & 127;
    if (n >= N_NODES) return;

    float4 acc = gather_node(hw, off, csr_src, csr_nrm, dis, n, lt);

    int c = lt * 4;
    float4 b  = *(const float4*)(bias + c);
    float4 wo = *(const float4*)(Wo + c);
    float4 ww = *(const float4*)(Ww + c);
    float r0 = fmaxf(acc.x + b.x, 0.f);
    float r1 = fmaxf(acc.y + b.y, 0.f);
    float r2 = fmaxf(acc.z + b.z, 0.f);
    float r3 = fmaxf(acc.w + b.w, 0.f);

    float so = r0 * wo.x + r1 * wo.y + r2 * wo.z + r3 * wo.w;
    float sw = r0 * ww.x + r1 * ww.y + r2 * ww.z + r3 * ww.w;

    #pragma unroll
    for (int o2 = 16; o2; o2 >>= 1) {
        so += __shfl_down_sync(0xffffffff, so, o2);
        sw += __shfl_down_sync(0xffffffff, sw, o2);
    }
    int warp = t >> 5, lane = t & 31;   // warps 0-3: node A, warps 4-7: node B
    if (lane == 0) { red[warp] = so; red[8 + warp] = sw; }
    __syncthreads();
    if (lt == 0) {
        int wb = (t >> 7) * 4;
        float fo = red[wb] + red[wb + 1] + red[wb + 2] + red[wb + 3];
        float fw = red[8 + wb] + red[8 + wb + 1] + red[8 + wb + 2] + red[8 + wb + 3];
        out[n]           = fo + bo[0];
        out[N_NODES + n] = fw + bw[0];
    }
}

// ---------------------------------------------------------------------------
// Launch — R12/R14 schedule (known-good)
// ---------------------------------------------------------------------------
extern "C" void kernel_launch(void* const* d_in, const int* in_sizes, int n_in,
                              void* d_out, int out_size) {
    const float* x  = (const float*)d_in[0];
    const int*   ei = (const int*)d_in[1];
    const float* W1 = (const float*)d_in[2];
    const float* b1 = (const float*)d_in[3];
    const float* W2 = (const float*)d_in[4];
    const float* b2 = (const float*)d_in[5];
    const float* Wo = (const float*)d_in[6];
    const float* bo = (const float*)d_in[7];
    const float* Ww = (const float*)d_in[8];
    const float* bw = (const float*)d_in[9];

    const int* src = ei;
    const int* dst = ei + E_EDGES;
    float* out = (float*)d_out;

    float *bufA, *dis, *csr_nrm;
    int *cnt, *off, *cur, *part, *boff, *csr_src;
    __nv_bfloat16 *Ah, *Al, *B1h, *B1l, *B2h, *B2l;
    cudaGetSymbolAddress((void**)&bufA, g_bufA);
    cudaGetSymbolAddress((void**)&dis,  g_dis);
    cudaGetSymbolAddress((void**)&cnt,  g_cnt);
    cudaGetSymbolAddress((void**)&off,  g_off);
    cudaGetSymbolAddress((void**)&cur,  g_cur);
    cudaGetSymbolAddress((void**)&part, g_part);
    cudaGetSymbolAddress((void**)&boff, g_boff);
    cudaGetSymbolAddress((void**)&csr_src, g_csr_src);
    cudaGetSymbolAddress((void**)&csr_nrm, g_csr_nrm);
    cudaGetSymbolAddress((void**)&Ah,   g_Ah);
    cudaGetSymbolAddress((void**)&Al,   g_Al);
    cudaGetSymbolAddress((void**)&B1h,  g_B1h);
    cudaGetSymbolAddress((void**)&B1l,  g_B1l);
    cudaGetSymbolAddress((void**)&B2h,  g_B2h);
    cudaGetSymbolAddress((void**)&B2l,  g_B2l);

    cudaFuncSetAttribute(gemm_wmma_kernel, cudaFuncAttributeMaxDynamicSharedMemorySize,
                         GEMM_SMEM_BYTES);

    cudaStream_t s1;
    cudaEvent_t evFork, evW, evJoin;
    cudaStreamCreateWithFlags(&s1, cudaStreamNonBlocking);
    cudaEventCreateWithFlags(&evFork, cudaEventDisableTiming);
    cudaEventCreateWithFlags(&evW,    cudaEventDisableTiming);
    cudaEventCreateWithFlags(&evJoin, cudaEventDisableTiming);

    const int NT = 256;
    int nb_edges = (E_EDGES + NT - 1) / NT;
    int nb_pack  = (MPAD * 128 + NT - 1) / NT;
    int nb_w2x   = (2 * 512 * 128 + NT - 1) / NT;
    int nb_gather = (N_NODES + 1) / 2;    // 12500 blocks x 256 thr

    // fork
    cudaEventRecord(evFork, 0);
    cudaStreamWaitEvent(s1, evFork, 0);

    // --- side stream: both weight packs, then CSR chain ---
    pack_w2x_kernel<<<nb_w2x, NT, 0, s1>>>(W1, B1h, B1l, W2, B2h, B2l);
    cudaEventRecord(evW, s1);
    cudaMemsetAsync(cnt, 0, N_NODES * sizeof(int), s1);
    cnt_count_kernel<<<nb_edges, NT, 0, s1>>>(dst, cnt);
    scan_part_kernel<<<SCAN_B, 1024, 0, s1>>>(cnt, off, part, dis);
    scan_top_kernel<<<1, 32, 0, s1>>>(part, boff, off);
    scan_apply_kernel<<<SCAN_B, 1024, 0, s1>>>(off, boff, cur);
    scatter_kernel<<<nb_edges, NT, 0, s1>>>(src, dst, cur, csr_src, csr_nrm, dis);
    cudaEventRecord(evJoin, s1);

    // --- main stream ---
    pack_x_kernel<<<nb_pack, NT>>>(x, Ah, Al);
    cudaStreamWaitEvent(0, evW, 0);

    dim3 ggrid(4, MT);
    gemm_wmma_kernel<<<ggrid, 256, GEMM_SMEM_BYTES>>>(Ah, Al, B1h, B1l, bufA);

    cudaStreamWaitEvent(0, evJoin, 0);

    gather_pack_kernel<<<nb_gather, 256>>>(bufA, off, csr_src, csr_nrm, dis, b1, Ah, Al);
    gemm_wmma_kernel<<<ggrid, 256, GEMM_SMEM_BYTES>>>(Ah, Al, B2h, B2l, bufA);
    gather_heads_kernel<<<nb_gather, 256>>>(bufA, off, csr_src, csr_nrm, dis, b2,
                                            Wo, bo, Ww, bw, out);
}

// round 16
// speedup vs baseline: 1.0414x; 1.0414x over previous
#include <cuda_runtime.h>
#include <cuda_bf16.h>
#include <mma.h>
#include <cstdint>

using namespace nvcuda;

#define N_NODES 25000
#define E_EDGES 200000
#define HID 512
#define MT 196
#define MPAD (MT * 128)        // 25088
#define SCAN_B 25

// ---------------------------------------------------------------------------
// Scratch (allocation-free: __device__ globals)
// ---------------------------------------------------------------------------
__device__ float g_bufA[MPAD * HID];
__device__ float g_dis[N_NODES];
__device__ int   g_cnt[N_NODES];
__device__ int   g_off[N_NODES + 1];
__device__ int   g_cur[N_NODES];
__device__ int   g_part[SCAN_B];
__device__ int   g_boff[SCAN_B];
__device__ int   g_csr_src[E_EDGES];
__device__ float g_csr_nrm[E_EDGES];
__device__ __nv_bfloat16 g_Ah[MPAD * HID];
__device__ __nv_bfloat16 g_Al[MPAD * HID];
__device__ __nv_bfloat16 g_B1h[HID * HID];
__device__ __nv_bfloat16 g_B1l[HID * HID];
__device__ __nv_bfloat16 g_B2h[HID * HID];
__device__ __nv_bfloat16 g_B2l[HID * HID];

// ---------------------------------------------------------------------------
// CSR build (distributed scan)
// ---------------------------------------------------------------------------
__global__ void cnt_count_kernel(const int* __restrict__ dst, int* cnt) {
    int e = blockIdx.x * blockDim.x + threadIdx.x;
    if (e < E_EDGES) atomicAdd(&cnt[dst[e]], 1);
}

__global__ __launch_bounds__(1024)
void scan_part_kernel(const int* __restrict__ cnt, int* __restrict__ off,
                      int* __restrict__ part, float* __restrict__ dis) {
    __shared__ int wsum[32];
    int b = blockIdx.x, t = threadIdx.x, lane = t & 31, warp = t >> 5;
    int idx = b * 1024 + t;
    int v = (idx < N_NODES) ? cnt[idx] : 0;
    if (idx < N_NODES) dis[idx] = rsqrtf((float)v + 1.0f);

    int incl = v;
    #pragma unroll
    for (int d = 1; d < 32; d <<= 1) {
        int u = __shfl_up_sync(0xffffffff, incl, d);
        if (lane >= d) incl += u;
    }
    if (lane == 31) wsum[warp] = incl;
    __syncthreads();
    if (warp == 0) {
        int w = wsum[lane];
        #pragma unroll
        for (int d = 1; d < 32; d <<= 1) {
            int u = __shfl_up_sync(0xffffffff, w, d);
            if (lane >= d) w += u;
        }
        wsum[lane] = w;
    }
    __syncthreads();
    int excl = incl - v + (warp ? wsum[warp - 1] : 0);
    if (idx < N_NODES) off[idx] = excl;
    if (t == 1023) part[b] = wsum[31];
}

__global__ void scan_top_kernel(const int* __restrict__ part, int* __restrict__ boff,
                                int* __restrict__ off) {
    int lane = threadIdx.x;
    int v = (lane < SCAN_B) ? part[lane] : 0;
    int incl = v;
    #pragma unroll
    for (int d = 1; d < 32; d <<= 1) {
        int u = __shfl_up_sync(0xffffffff, incl, d);
        if (lane >= d) incl += u;
    }
    if (lane < SCAN_B) boff[lane] = incl - v;
    if (lane == 31) off[N_NODES] = incl;
}

__global__ __launch_bounds__(1024)
void scan_apply_kernel(int* __restrict__ off, const int* __restrict__ boff,
                       int* __restrict__ cur) {
    int b = blockIdx.x, t = threadIdx.x;
    int idx = b * 1024 + t;
    if (idx < N_NODES) {
        int o = off[idx] + boff[b];
        off[idx] = o;
        cur[idx] = o;
    }
}

// scatter also precomputes per-edge symmetric norm (dis is ready by now)
__global__ void scatter_kernel(const int* __restrict__ src, const int* __restrict__ dst,
                               int* cur, int* __restrict__ csr_src,
                               float* __restrict__ csr_nrm,
                               const float* __restrict__ dis) {
    int e = blockIdx.x * blockDim.x + threadIdx.x;
    if (e >= E_EDGES) return;
    int s = src[e], d = dst[e];
    int pos = atomicAdd(&cur[d], 1);
    csr_src[pos] = s;
    csr_nrm[pos] = __ldg(&dis[s]) * __ldg(&dis[d]);
}

// ---------------------------------------------------------------------------
// Packing (float4/thread)
// ---------------------------------------------------------------------------
__device__ __forceinline__ void split4_store(float r0, float r1, float r2, float r3,
                                             __nv_bfloat16* outH, __nv_bfloat16* outL,
                                             size_t o) {
    __nv_bfloat16 h0 = __float2bfloat16_rn(r0), h1 = __float2bfloat16_rn(r1);
    __nv_bfloat16 h2 = __float2bfloat16_rn(r2), h3 = __float2bfloat16_rn(r3);
    __nv_bfloat16 l0 = __float2bfloat16_rn(r0 - __bfloat162float(h0));
    __nv_bfloat16 l1 = __float2bfloat16_rn(r1 - __bfloat162float(h1));
    __nv_bfloat16 l2 = __float2bfloat16_rn(r2 - __bfloat162float(h2));
    __nv_bfloat16 l3 = __float2bfloat16_rn(r3 - __bfloat162float(h3));
    __nv_bfloat162 ph0(h0, h1), ph1(h2, h3), pl0(l0, l1), pl1(l2, l3);
    uint2 uh = make_uint2(*(uint32_t*)&ph0, *(uint32_t*)&ph1);
    uint2 ul = make_uint2(*(uint32_t*)&pl0, *(uint32_t*)&pl1);
    *(uint2*)(outH + o) = uh;
    *(uint2*)(outL + o) = ul;
}

__global__ __launch_bounds__(256)
void pack_x_kernel(const float* __restrict__ src,
                   __nv_bfloat16* __restrict__ outH, __nv_bfloat16* __restrict__ outL) {
    int idx = blockIdx.x * blockDim.x + threadIdx.x;
    if (idx >= MPAD * 128) return;
    int m = idx >> 7;
    int k = (idx & 127) * 4;

    float4 v = make_float4(0.f, 0.f, 0.f, 0.f);
    if (m < N_NODES) v = *(const float4*)(src + (size_t)m * HID + k);
    split4_store(v.x, v.y, v.z, v.w, outH, outL, (size_t)m * HID + k);
}

__global__ __launch_bounds__(256)
void pack_w2x_kernel(const float* __restrict__ W1,
                     __nv_bfloat16* __restrict__ o1H, __nv_bfloat16* __restrict__ o1L,
                     const float* __restrict__ W2,
                     __nv_bfloat16* __restrict__ o2H, __nv_bfloat16* __restrict__ o2L) {
    int idx = blockIdx.x * blockDim.x + threadIdx.x;
    if (idx >= 2 * 512 * 128) return;
    int z = idx >= 512 * 128;
    int r = z ? idx - 512 * 128 : idx;
    int k = r >> 7;
    int n = (r & 127) * 4;

    const float* W = z ? W2 : W1;
    __nv_bfloat16* oH = z ? o2H : o1H;
    __nv_bfloat16* oL = z ? o2L : o1L;

    float4 v = *(const float4*)(W + (size_t)k * HID + n);
    split4_store(v.x, v.y, v.z, v.w, oH, oL, (size_t)k * HID + n);
}

// ---------------------------------------------------------------------------
// cp.async helpers
// ---------------------------------------------------------------------------
__device__ __forceinline__ void cpa16(uint32_t dst, const void* src) {
    asm volatile("cp.async.cg.shared.global [%0], [%1], 16;" :: "r"(dst), "l"(src));
}
__device__ __forceinline__ void cpa_commit() {
    asm volatile("cp.async.commit_group;" ::: "memory");
}
__device__ __forceinline__ void cpa_wait0() {
    asm volatile("cp.async.wait_group 0;" ::: "memory");
}

// ---------------------------------------------------------------------------
// WMMA bf16-split GEMM (known-good). DO NOT grow smem (2-CTA/SM, R8/R10);
// DO NOT split M (wave quantization, R13).
// ---------------------------------------------------------------------------
#define AS_STRIDE 40
#define BS_STRIDE 136
#define A_TILE_ELE (128 * AS_STRIDE)
#define B_TILE_ELE (32 * BS_STRIDE)
#define STAGE_ELE  (2 * A_TILE_ELE + 2 * B_TILE_ELE)
#define GEMM_SMEM_BYTES (2 * STAGE_ELE * 2)

__global__ __launch_bounds__(256, 2)
void gemm_wmma_kernel(const __nv_bfloat16* __restrict__ Ah, const __nv_bfloat16* __restrict__ Al,
                      const __nv_bfloat16* __restrict__ Bh, const __nv_bfloat16* __restrict__ Bl,
                      float* __restrict__ C) {
    extern __shared__ __nv_bfloat16 smem[];

    int tid = threadIdx.x;
    int bm = blockIdx.y * 128;
    int bn = blockIdx.x * 128;
    int wid = tid >> 5;
    int wm = (wid & 3) * 32;
    int wn = (wid >> 2) * 64;

    wmma::fragment<wmma::accumulator, 16, 16, 16, float> acc[2][4];
    #pragma unroll
    for (int i = 0; i < 2; i++)
        #pragma unroll
        for (int j = 0; j < 4; j++)
            wmma::fill_fragment(acc[i][j], 0.0f);

    int a_r0 = tid >> 2,  a_c0 = (tid & 3) * 8;
    int a_r1 = (tid + 256) >> 2, a_c1 = ((tid + 256) & 3) * 8;
    int b_r0 = tid >> 4,  b_c0 = (tid & 15) * 8;
    int b_r1 = (tid + 256) >> 4, b_c1 = ((tid + 256) & 15) * 8;

    uint32_t sbase = (uint32_t)__cvta_generic_to_shared(smem);

    auto load_stage = [&](int stage, int k0) {
        uint32_t st = sbase + (uint32_t)(stage * STAGE_ELE) * 2;
        uint32_t sAh = st;
        uint32_t sAl = st + A_TILE_ELE * 2;
        uint32_t sBh = st + 2 * A_TILE_ELE * 2;
        uint32_t sBl = st + (2 * A_TILE_ELE + B_TILE_ELE) * 2;

        const __nv_bfloat16* gA = Ah + (size_t)bm * HID + k0;
        const __nv_bfloat16* gAl2 = Al + (size_t)bm * HID + k0;
        const __nv_bfloat16* gB = Bh + (size_t)k0 * HID + bn;
        const __nv_bfloat16* gBl2 = Bl + (size_t)k0 * HID + bn;

        cpa16(sAh + (uint32_t)(a_r0 * AS_STRIDE + a_c0) * 2, gA  + (size_t)a_r0 * HID + a_c0);
        cpa16(sAh + (uint32_t)(a_r1 * AS_STRIDE + a_c1) * 2, gA  + (size_t)a_r1 * HID + a_c1);
        cpa16(sAl + (uint32_t)(a_r0 * AS_STRIDE + a_c0) * 2, gAl2 + (size_t)a_r0 * HID + a_c0);
        cpa16(sAl + (uint32_t)(a_r1 * AS_STRIDE + a_c1) * 2, gAl2 + (size_t)a_r1 * HID + a_c1);
        cpa16(sBh + (uint32_t)(b_r0 * BS_STRIDE + b_c0) * 2, gB  + (size_t)b_r0 * HID + b_c0);
        cpa16(sBh + (uint32_t)(b_r1 * BS_STRIDE + b_c1) * 2, gB  + (size_t)b_r1 * HID + b_c1);
        cpa16(sBl + (uint32_t)(b_r0 * BS_STRIDE + b_c0) * 2, gBl2 + (size_t)b_r0 * HID + b_c0);
        cpa16(sBl + (uint32_t)(b_r1 * BS_STRIDE + b_c1) * 2, gBl2 + (size_t)b_r1 * HID + b_c1);
        cpa_commit();
    };

    load_stage(0, 0);
    int buf = 0;

    for (int it = 0; it < 16; it++) {
        cpa_wait0();
        __syncthreads();
        if (it + 1 < 16) load_stage(buf ^ 1, (it + 1) * 32);

        __nv_bfloat16* st = smem + buf * STAGE_ELE;
        __nv_bfloat16* Ash = st;
        __nv_bfloat16* Asl = st + A_TILE_ELE;
        __nv_bfloat16* Bsh = st + 2 * A_TILE_ELE;
        __nv_bfloat16* Bsl = st + 2 * A_TILE_ELE + B_TILE_ELE;

        #pragma unroll
        for (int kk = 0; kk < 32; kk += 16) {
            wmma::fragment<wmma::matrix_a, 16, 16, 16, __nv_bfloat16, wmma::row_major> fa_h[2], fa_l[2];
            wmma::fragment<wmma::matrix_b, 16, 16, 16, __nv_bfloat16, wmma::row_major> fb_h[4], fb_l[4];
            #pragma unroll
            for (int i = 0; i < 2; i++) {
                wmma::load_matrix_sync(fa_h[i], Ash + (wm + i * 16) * AS_STRIDE + kk, AS_STRIDE);
                wmma::load_matrix_sync(fa_l[i], Asl + (wm + i * 16) * AS_STRIDE + kk, AS_STRIDE);
            }
            #pragma unroll
            for (int j = 0; j < 4; j++) {
                wmma::load_matrix_sync(fb_h[j], Bsh + kk * BS_STRIDE + wn + j * 16, BS_STRIDE);
                wmma::load_matrix_sync(fb_l[j], Bsl + kk * BS_STRIDE + wn + j * 16, BS_STRIDE);
            }
            #pragma unroll
            for (int i = 0; i < 2; i++)
                #pragma unroll
                for (int j = 0; j < 4; j++) {
                    wmma::mma_sync(acc[i][j], fa_h[i], fb_h[j], acc[i][j]);
                    wmma::mma_sync(acc[i][j], fa_l[i], fb_h[j], acc[i][j]);
                    wmma::mma_sync(acc[i][j], fa_h[i], fb_l[j], acc[i][j]);
                }
        }
        buf ^= 1;
    }

    #pragma unroll
    for (int i = 0; i < 2; i++)
        #pragma unroll
        for (int j = 0; j < 4; j++)
            wmma::store_matrix_sync(C + (size_t)(bm + wm + i * 16) * HID + bn + wn + j * 16,
                                    acc[i][j], HID, wmma::mem_row_major);
}

// ---------------------------------------------------------------------------
// Gather: 1 node per 128-thread block (R14 geometry); precomputed edge norms;
// warp-shuffle broadcast (no barriers in the inner loop).
// ---------------------------------------------------------------------------
__device__ __forceinline__ float4 gather_node(const float* __restrict__ hw,
                                              const int* __restrict__ off,
                                              const int* __restrict__ csr_src,
                                              const float* __restrict__ csr_nrm,
                                              const float* __restrict__ dis,
                                              int n, int t) {
    float dn = __ldg(&dis[n]);
    const float4* hn = (const float4*)(hw + (size_t)n * HID);
    float4 v = hn[t];
    float dd = dn * dn;
    float4 acc = make_float4(v.x * dd, v.y * dd, v.z * dd, v.w * dd);

    int lane = t & 31;
    int beg = __ldg(&off[n]), end = __ldg(&off[n + 1]);
    for (int base = beg; base < end; base += 32) {
        int m = min(32, end - base);
        int s = 0; float nrm = 0.f;
        if (lane < m) {
            s   = __ldg(&csr_src[base + lane]);
            nrm = __ldg(&csr_nrm[base + lane]);
        }
        #pragma unroll 8
        for (int j = 0; j < m; j++) {
            int sj   = __shfl_sync(0xffffffff, s, j);
            float nj = __shfl_sync(0xffffffff, nrm, j);
            float4 h = ((const float4*)(hw + (size_t)sj * HID))[t];
            acc.x = fmaf(h.x, nj, acc.x);
            acc.y = fmaf(h.y, nj, acc.y);
            acc.z = fmaf(h.z, nj, acc.z);
            acc.w = fmaf(h.w, nj, acc.w);
        }
    }
    return acc;
}

__global__ __launch_bounds__(128)
void gather_pack_kernel(const float* __restrict__ hw,
                        const int* __restrict__ off, const int* __restrict__ csr_src,
                        const float* __restrict__ csr_nrm, const float* __restrict__ dis,
                        const float* __restrict__ bias,
                        __nv_bfloat16* __restrict__ outH, __nv_bfloat16* __restrict__ outL) {
    int n = blockIdx.x;
    int t = threadIdx.x;

    float4 acc = gather_node(hw, off, csr_src, csr_nrm, dis, n, t);

    int c = t * 4;
    float4 b = *(const float4*)(bias + c);
    float r0 = fmaxf(acc.x + b.x, 0.f);
    float r1 = fmaxf(acc.y + b.y, 0.f);
    float r2 = fmaxf(acc.z + b.z, 0.f);
    float r3 = fmaxf(acc.w + b.w, 0.f);

    split4_store(r0, r1, r2, r3, outH, outL, (size_t)n * HID + c);
}

__global__ __launch_bounds__(128)
void gather_heads_kernel(const float* __restrict__ hw,
                         const int* __restrict__ off, const int* __restrict__ csr_src,
                         const float* __restrict__ csr_nrm, const float* __restrict__ dis,
                         const float* __restrict__ bias,
                         const float* __restrict__ Wo, const float* __restrict__ bo,
                         const float* __restrict__ Ww, const float* __restrict__ bw,
                         float* __restrict__ out) {
    __shared__ float red[8];
    int n = blockIdx.x;
    int t = threadIdx.x;

    float4 acc = gather_node(hw, off, csr_src, csr_nrm, dis, n, t);

    int c = t * 4;
    float4 b  = *(const float4*)(bias + c);
    float4 wo = *(const float4*)(Wo + c);
    float4 ww = *(const float4*)(Ww + c);
    float r0 = fmaxf(acc.x + b.x, 0.f);
    float r1 = fmaxf(acc.y + b.y, 0.f);
    float r2 = fmaxf(acc.z + b.z, 0.f);
    float r3 = fmaxf(acc.w + b.w, 0.f);

    float so = r0 * wo.x + r1 * wo.y + r2 * wo.z + r3 * wo.w;
    float sw = r0 * ww.x + r1 * ww.y + r2 * ww.z + r3 * ww.w;

    #pragma unroll
    for (int o2 = 16; o2; o2 >>= 1) {
        so += __shfl_down_sync(0xffffffff, so, o2);
        sw += __shfl_down_sync(0xffffffff, sw, o2);
    }
    int warp = t >> 5, lane = t & 31;
    if (lane == 0) { red[warp] = so; red[4 + warp] = sw; }
    __syncthreads();
    if (t == 0) {
        float fo = red[0] + red[1] + red[2] + red[3];
        float fw = red[4] + red[5] + red[6] + red[7];
        out[n]           = fo + bo[0];
        out[N_NODES + n] = fw + bw[0];
    }
}

// ---------------------------------------------------------------------------
// Launch — R12/R14 schedule (known-good)
// ---------------------------------------------------------------------------
extern "C" void kernel_launch(void* const* d_in, const int* in_sizes, int n_in,
                              void* d_out, int out_size) {
    const float* x  = (const float*)d_in[0];
    const int*   ei = (const int*)d_in[1];
    const float* W1 = (const float*)d_in[2];
    const float* b1 = (const float*)d_in[3];
    const float* W2 = (const float*)d_in[4];
    const float* b2 = (const float*)d_in[5];
    const float* Wo = (const float*)d_in[6];
    const float* bo = (const float*)d_in[7];
    const float* Ww = (const float*)d_in[8];
    const float* bw = (const float*)d_in[9];

    const int* src = ei;
    const int* dst = ei + E_EDGES;
    float* out = (float*)d_out;

    float *bufA, *dis, *csr_nrm;
    int *cnt, *off, *cur, *part, *boff, *csr_src;
    __nv_bfloat16 *Ah, *Al, *B1h, *B1l, *B2h, *B2l;
    cudaGetSymbolAddress((void**)&bufA, g_bufA);
    cudaGetSymbolAddress((void**)&dis,  g_dis);
    cudaGetSymbolAddress((void**)&cnt,  g_cnt);
    cudaGetSymbolAddress((void**)&off,  g_off);
    cudaGetSymbolAddress((void**)&cur,  g_cur);
    cudaGetSymbolAddress((void**)&part, g_part);
    cudaGetSymbolAddress((void**)&boff, g_boff);
    cudaGetSymbolAddress((void**)&csr_src, g_csr_src);
    cudaGetSymbolAddress((void**)&csr_nrm, g_csr_nrm);
    cudaGetSymbolAddress((void**)&Ah,   g_Ah);
    cudaGetSymbolAddress((void**)&Al,   g_Al);
    cudaGetSymbolAddress((void**)&B1h,  g_B1h);
    cudaGetSymbolAddress((void**)&B1l,  g_B1l);
    cudaGetSymbolAddress((void**)&B2h,  g_B2h);
    cudaGetSymbolAddress((void**)&B2l,  g_B2l);

    cudaFuncSetAttribute(gemm_wmma_kernel, cudaFuncAttributeMaxDynamicSharedMemorySize,
                         GEMM_SMEM_BYTES);

    cudaStream_t s1;
    cudaEvent_t evFork, evW, evJoin;
    cudaStreamCreateWithFlags(&s1, cudaStreamNonBlocking);
    cudaEventCreateWithFlags(&evFork, cudaEventDisableTiming);
    cudaEventCreateWithFlags(&evW,    cudaEventDisableTiming);
    cudaEventCreateWithFlags(&evJoin, cudaEventDisableTiming);

    const int NT = 256;
    int nb_edges = (E_EDGES + NT - 1) / NT;
    int nb_pack  = (MPAD * 128 + NT - 1) / NT;
    int nb_w2x   = (2 * 512 * 128 + NT - 1) / NT;

    // fork
    cudaEventRecord(evFork, 0);
    cudaStreamWaitEvent(s1, evFork, 0);

    // --- side stream: both weight packs, then CSR chain ---
    pack_w2x_kernel<<<nb_w2x, NT, 0, s1>>>(W1, B1h, B1l, W2, B2h, B2l);
    cudaEventRecord(evW, s1);
    cudaMemsetAsync(cnt, 0, N_NODES * sizeof(int), s1);
    cnt_count_kernel<<<nb_edges, NT, 0, s1>>>(dst, cnt);
    scan_part_kernel<<<SCAN_B, 1024, 0, s1>>>(cnt, off, part, dis);
    scan_top_kernel<<<1, 32, 0, s1>>>(part, boff, off);
    scan_apply_kernel<<<SCAN_B, 1024, 0, s1>>>(off, boff, cur);
    scatter_kernel<<<nb_edges, NT, 0, s1>>>(src, dst, cur, csr_src, csr_nrm, dis);
    cudaEventRecord(evJoin, s1);

    // --- main stream ---
    pack_x_kernel<<<nb_pack, NT>>>(x, Ah, Al);
    cudaStreamWaitEvent(0, evW, 0);

    dim3 ggrid(4, MT);
    gemm_wmma_kernel<<<ggrid, 256, GEMM_SMEM_BYTES>>>(Ah, Al, B1h, B1l, bufA);

    cudaStreamWaitEvent(0, evJoin, 0);

    gather_pack_kernel<<<N_NODES, 128>>>(bufA, off, csr_src, csr_nrm, dis, b1, Ah, Al);
    gemm_wmma_kernel<<<ggrid, 256, GEMM_SMEM_BYTES>>>(Ah, Al, B2h, B2l, bufA);
    gather_heads_kernel<<<N_NODES, 128>>>(bufA, off, csr_src, csr_nrm, dis, b2,
                                          Wo, bo, Ww, bw, out);
}